// round 2
// baseline (speedup 1.0000x reference)
#include <cuda_runtime.h>

// NVAR feature expansion.
// X: (8,4,4096) f32  ->  out: (8,4,3996,231) f32
//   out[br, t, 0]        = 1
//   out[br, t, 1+k]      = X[br, t + 82 + 2k]            (k = 0..9)
//   out[br, t, 11+m]     = lin[a]*lin[b]*lin[c]          (m-th lex triple a<=b<=c from 0..9)
// (TRANSIENTS=100 > pad=18 so the zero padding never appears in the output.)
//
// Strategy: pure store-bandwidth problem (118 MB out, 512 KB in).
// Flat-tile the output in 16384-float chunks per block; all stores are
// aligned float4 (total floats % 4 == 0). Tap values for the covered
// time points are staged in shared, monomial index table built in shared.

constexpr int K_TAPS   = 10;
constexpr int SKIP     = 2;
constexpr int N_MONO   = 220;          // C(12,3)
constexpr int NF       = 231;          // 1 + 10 + 220
constexpr int N_TIME   = 4096;
constexpr int T_OUT    = 3996;         // 4096 - TRANSIENTS
constexpr int N_BR     = 32;           // 8*4
constexpr int NP_TOT   = N_BR * T_OUT;      // 127872 points
constexpr int TOTAL_F  = NP_TOT * NF;       // 29538432 floats (divisible by 4)
constexpr int BASE_OFF = 82;           // TRANSIENTS - pad = 100 - 18

constexpr int BLK  = 256;
constexpr int VPT  = 16;               // float4s per thread
constexpr int FPB  = BLK * VPT * 4;    // 16384 floats per block
constexpr int GRID = (TOTAL_F + FPB - 1) / FPB;   // 1803

__global__ __launch_bounds__(BLK) void nvar_kernel(const float* __restrict__ X,
                                                   float* __restrict__ out) {
    __shared__ float    s_lin[80][K_TAPS];   // up to 72 points covered per block
    __shared__ unsigned s_mono[N_MONO];      // packed (a | b<<8 | c<<16)

    const int tid  = threadIdx.x;
    const int base = blockIdx.x * FPB;

    // Build the lexicographic combinations-with-replacement index table.
    for (int m = tid; m < N_MONO; m += BLK) {
        int rem = m, a = 0;
        for (;;) { int cnt = (K_TAPS - a) * (K_TAPS + 1 - a) / 2; if (rem < cnt) break; rem -= cnt; ++a; }
        int b = a;
        for (;;) { int cnt = K_TAPS - b; if (rem < cnt) break; rem -= cnt; ++b; }
        int c = b + rem;
        s_mono[m] = (unsigned)a | ((unsigned)b << 8) | ((unsigned)c << 16);
    }

    // Which output points does this block touch?
    const int p0   = base / NF;
    int       lastf = base + FPB - 1;
    if (lastf >= TOTAL_F) lastf = TOTAL_F - 1;
    const int p1 = lastf / NF;
    const int np = p1 - p0 + 1;                // <= 72

    // Stage the tap values for those points in shared.
    for (int l = tid; l < np * K_TAPS; l += BLK) {
        const int dp = l / K_TAPS;
        const int k  = l - dp * K_TAPS;
        const int p  = p0 + dp;
        const int br = p / T_OUT;
        const int t  = p - br * T_OUT;
        s_lin[dp][k] = X[br * N_TIME + t + BASE_OFF + SKIP * k];
    }
    __syncthreads();

    #pragma unroll
    for (int c = 0; c < VPT; ++c) {
        const int j = base + (tid + c * BLK) * 4;     // aligned float4 index
        if (j < TOTAL_F) {
            int p  = j / NF;
            int f  = j - p * NF;
            int dp = p - p0;

            float v[4];
            #pragma unroll
            for (int e = 0; e < 4; ++e) {
                float val;
                if (f == 0) {
                    val = 1.0f;
                } else if (f <= K_TAPS) {
                    val = s_lin[dp][f - 1];
                } else {
                    const unsigned tr = s_mono[f - 11];
                    val = s_lin[dp][tr & 0xFF]
                        * s_lin[dp][(tr >> 8) & 0xFF]
                        * s_lin[dp][(tr >> 16) & 0xFF];
                }
                v[e] = val;
                if (++f == NF) { f = 0; ++dp; }
            }
            *reinterpret_cast<float4*>(out + j) =
                make_float4(v[0], v[1], v[2], v[3]);
        }
    }
}

extern "C" void kernel_launch(void* const* d_in, const int* in_sizes, int n_in,
                              void* d_out, int out_size) {
    const float* X   = (const float*)d_in[0];
    float*       out = (float*)d_out;
    (void)in_sizes; (void)n_in; (void)out_size;
    nvar_kernel<<<GRID, BLK>>>(X, out);
}

// round 4
// speedup vs baseline: 1.5490x; 1.5490x over previous
#include <cuda_runtime.h>

// NVAR feature expansion.  X: (8,4,4096) f32 -> out: (8,4,3996,231) f32
//   out[p, 0]      = 1
//   out[p, 1+k]    = lin[k] = X[br, t + 82 + 2k]
//   out[p, 11+m]   = lin[a]*lin[b]*lin[c], lex triples a<=b<=c over 0..9
//
// R2 strategy: one thread per point, taps in registers, fully unrolled
// compile-time monomial loop with pair-product CSE (275 FMUL + 231 STS per
// point). Stage into packed shared (lane stride 231 words = 7 mod 32 ->
// conflict-free), then coalesced float4 copy to global.

constexpr int K_TAPS   = 10;
constexpr int NF       = 231;          // 1 + 10 + 220
constexpr int N_TIME   = 4096;
constexpr int T_OUT    = 3996;
constexpr int BASE_OFF = 82;           // TRANSIENTS - (K-1)*SKIP
constexpr int SKIP     = 2;

constexpr int NP_BLK   = 96;                       // points (= threads) per CTA
constexpr int FL_BLK   = NP_BLK * NF;              // 22176 floats per CTA (div by 4)
constexpr int V4_BLK   = FL_BLK / 4;               // 5544 float4
constexpr int GRID     = (8 * 4 * T_OUT) / NP_BLK; // 1332 exactly
constexpr int SMEM_B   = FL_BLK * 4;               // 88704 bytes

__global__ __launch_bounds__(NP_BLK) void nvar_kernel(const float* __restrict__ X,
                                                      float* __restrict__ out) {
    extern __shared__ float s_feat[];              // packed: point-major, stride NF

    const int tid = threadIdx.x;
    const int p   = blockIdx.x * NP_BLK + tid;     // global point id
    const int br  = p / T_OUT;
    const int t   = p - br * T_OUT;

    // ---- Phase 1: compute all 231 features of this thread's point ----
    float lin[K_TAPS];
    const float* xb = X + br * N_TIME + t + BASE_OFF;
    #pragma unroll
    for (int k = 0; k < K_TAPS; ++k) lin[k] = xb[SKIP * k];

    float* o = s_feat + tid * NF;
    o[0] = 1.0f;
    #pragma unroll
    for (int k = 0; k < K_TAPS; ++k) o[1 + k] = lin[k];

    int m = 11;                                    // resolved at compile time
    #pragma unroll
    for (int a = 0; a < K_TAPS; ++a) {
        #pragma unroll
        for (int b = a; b < K_TAPS; ++b) {
            const float pab = lin[a] * lin[b];
            #pragma unroll
            for (int c = b; c < K_TAPS; ++c) {
                o[m++] = pab * lin[c];
            }
        }
    }
    __syncthreads();

    // ---- Phase 2: coalesced float4 copy shared -> global ----
    const float4* s4 = reinterpret_cast<const float4*>(s_feat);
    float4*       g4 = reinterpret_cast<float4*>(out) + blockIdx.x * V4_BLK;
    for (int i = tid; i < V4_BLK; i += NP_BLK) {
        g4[i] = s4[i];
    }
}

extern "C" void kernel_launch(void* const* d_in, const int* in_sizes, int n_in,
                              void* d_out, int out_size) {
    const float* X   = (const float*)d_in[0];
    float*       out = (float*)d_out;
    (void)in_sizes; (void)n_in; (void)out_size;
    cudaFuncSetAttribute(nvar_kernel,
                         cudaFuncAttributeMaxDynamicSharedMemorySize, SMEM_B);
    nvar_kernel<<<GRID, NP_BLK, SMEM_B>>>(X, out);
}

// round 5
// speedup vs baseline: 1.8343x; 1.1841x over previous
#include <cuda_runtime.h>

// NVAR feature expansion.  X: (8,4,4096) f32 -> out: (8,4,3996,231) f32
//   out[p, 0]      = 1
//   out[p, 1+k]    = lin[k] = X[br, t + 82 + 2k]
//   out[p, 11+m]   = lin[a]*lin[b]*lin[c], lex triples a<=b<=c over 0..9
//
// R4: CTA = 128 threads / 32 points / 29.6 KB smem (7 CTAs/SM -> ~87% occ).
// Warp q computes compile-time feature segment q for all 32 points (lane =
// point); constant-index STS, stride 231 (gcd(7,32)=1, conflict-free).
// Then all 128 threads copy the tile to global as aligned float4.

constexpr int K_TAPS   = 10;
constexpr int NF       = 231;
constexpr int N_TIME   = 4096;
constexpr int T_OUT    = 3996;
constexpr int BASE_OFF = 82;           // TRANSIENTS - (K-1)*SKIP
constexpr int SKIP     = 2;

constexpr int NP_BLK   = 32;                        // points per CTA
constexpr int NTHREADS = 128;
constexpr int NSEG     = 4;
constexpr int FL_BLK   = NP_BLK * NF;               // 7392 floats (div by 4)
constexpr int V4_BLK   = FL_BLK / 4;                // 1848 float4
constexpr int GRID     = (8 * 4 * T_OUT) / NP_BLK;  // 3996 exactly
constexpr int SMEM_B   = FL_BLK * 4;                // 29568 bytes

// Segment boundaries over the 231 features.
__device__ constexpr int SEG_LO[NSEG + 1] = {0, 58, 116, 174, 231};

__global__ __launch_bounds__(NTHREADS) void nvar_kernel(const float* __restrict__ X,
                                                        float* __restrict__ out) {
    extern __shared__ float s_feat[];               // point-major, stride NF

    const int tid = threadIdx.x;
    const int q   = tid >> 5;                       // warp = feature segment
    const int lp  = tid & 31;                       // lane = local point
    const int p   = blockIdx.x * NP_BLK + lp;
    const int br  = p / T_OUT;
    const int t   = p - br * T_OUT;

    // ---- Phase 1: taps in registers, compile-time segment emission ----
    float lin[K_TAPS];
    const float* xb = X + br * N_TIME + t + BASE_OFF;
    #pragma unroll
    for (int k = 0; k < K_TAPS; ++k) lin[k] = xb[SKIP * k];

    float* o = s_feat + lp * NF;

    #pragma unroll
    for (int Q = 0; Q < NSEG; ++Q) {
        if (q == Q) {
            const int lo = SEG_LO[Q];
            const int hi = SEG_LO[Q + 1];
            if (Q == 0) {
                o[0] = 1.0f;
                #pragma unroll
                for (int k = 0; k < K_TAPS; ++k) o[1 + k] = lin[k];
            }
            int m = 11;                             // compile-time after unroll
            #pragma unroll
            for (int a = 0; a < K_TAPS; ++a) {
                #pragma unroll
                for (int b = a; b < K_TAPS; ++b) {
                    const float pab = lin[a] * lin[b];
                    #pragma unroll
                    for (int c = b; c < K_TAPS; ++c) {
                        if (m >= lo && m < hi) o[m] = pab * lin[c];
                        ++m;
                    }
                }
            }
        }
    }
    __syncthreads();

    // ---- Phase 2: coalesced float4 copy shared -> global ----
    const float4* s4 = reinterpret_cast<const float4*>(s_feat);
    float4*       g4 = reinterpret_cast<float4*>(out) + blockIdx.x * V4_BLK;
    #pragma unroll
    for (int i = tid; i < V4_BLK; i += NTHREADS) {
        g4[i] = s4[i];
    }
}

extern "C" void kernel_launch(void* const* d_in, const int* in_sizes, int n_in,
                              void* d_out, int out_size) {
    const float* X   = (const float*)d_in[0];
    float*       out = (float*)d_out;
    (void)in_sizes; (void)n_in; (void)out_size;
    nvar_kernel<<<GRID, NTHREADS, SMEM_B>>>(X, out);
}